// round 7
// baseline (speedup 1.0000x reference)
#include <cuda_runtime.h>

#define FULL_MASK 0xFFFFFFFFu

// ---- packed f32x2 helpers (sm_103a FFMA2/FMUL2 via PTX) ----
__device__ __forceinline__ unsigned long long pack2(float lo, float hi) {
    unsigned long long r;
    asm("mov.b64 %0, {%1, %2};" : "=l"(r) : "f"(lo), "f"(hi));
    return r;
}
__device__ __forceinline__ void unpack2(unsigned long long v, float& lo, float& hi) {
    asm("mov.b64 {%0, %1}, %2;" : "=f"(lo), "=f"(hi) : "l"(v));
}
__device__ __forceinline__ unsigned long long fma2(unsigned long long a,
                                                   unsigned long long b,
                                                   unsigned long long c) {
    unsigned long long r;
    asm("fma.rn.f32x2 %0, %1, %2, %3;" : "=l"(r) : "l"(a), "l"(b), "l"(c));
    return r;
}
__device__ __forceinline__ unsigned long long mul2(unsigned long long a,
                                                   unsigned long long b) {
    unsigned long long r;
    asm("mul.rn.f32x2 %0, %1, %2;" : "=l"(r) : "l"(a), "l"(b));
    return r;
}

// A 128-elem row's 4 per-lane floats, held as two packed f32x2.
struct Row { unsigned long long p0, p1; };  // (x,y), (z,w)

// In-register butterfly stages over index bits 0,1.
__device__ __forceinline__ Row stage12(float4 v) {
    float a = v.x + v.y, b = v.x - v.y;
    float c = v.z + v.w, d = v.z - v.w;
    Row r;
    r.p0 = pack2(a + c, b + d);
    r.p1 = pack2(a - c, b - d);
    return r;
}

// One cross-lane butterfly stage: v = fma(v, sgn, partner).
// sgn = -1 where (lane & mask), else +1. Bit-exact with (o-v)/(v+o).
__device__ __forceinline__ void xstage(Row& r, unsigned long long sgn, int mask) {
    float x, y, z, w;
    unpack2(r.p0, x, y);
    unpack2(r.p1, z, w);
    float ox = __shfl_xor_sync(FULL_MASK, x, mask);
    float oy = __shfl_xor_sync(FULL_MASK, y, mask);
    float oz = __shfl_xor_sync(FULL_MASK, z, mask);
    float ow = __shfl_xor_sync(FULL_MASK, w, mask);
    r.p0 = fma2(r.p0, sgn, pack2(ox, oy));
    r.p1 = fma2(r.p1, sgn, pack2(oz, ow));
}

__device__ __forceinline__ float4 row_to_f4(Row r) {
    float4 v;
    unpack2(r.p0, v.x, v.y);
    unpack2(r.p1, v.z, v.w);
    return v;
}

// 4-bit symmetric fake-quant of a rotated+scaled k row; streaming store.
__device__ __forceinline__ void quant_store(float4* __restrict__ p, long long idx, Row r) {
    float x, y, z, w;
    unpack2(r.p0, x, y);
    unpack2(r.p1, z, w);
    float amax = fmaxf(fmaxf(fabsf(x), fabsf(y)), fmaxf(fabsf(z), fabsf(w)));
#pragma unroll
    for (int m = 16; m >= 1; m >>= 1)
        amax = fmaxf(amax, __shfl_xor_sync(FULL_MASK, amax, m));
    if (amax == 0.0f) amax = 1.0f;
    const float qscale = amax / 7.0f;   // single rounding, matches reference
    const float qinv = 1.0f / qscale;
    float4 v;
    v.x = fminf(fmaxf(rintf(x * qinv), -8.0f), 7.0f) * qscale;
    v.y = fminf(fmaxf(rintf(y * qinv), -8.0f), 7.0f) * qscale;
    v.z = fminf(fmaxf(rintf(z * qinv), -8.0f), 7.0f) * qscale;
    v.w = fminf(fmaxf(rintf(w * qinv), -8.0f), 7.0f) * qscale;
    __stcs(p + idx, v);
}

// Persistent grid-stride warps with depth-1 prefetch.
// Each iteration: 2 q rows + 2 k rows (group = 2 row-indices, 64 float4).
// While computing group g, loads for group g+stride are in flight, so the
// memory pipe never drains during the shfl chains.
__global__ void __launch_bounds__(256)
qk_rot_quant_kernel(const float4* __restrict__ qin,
                    const float4* __restrict__ kin,
                    float4* __restrict__ qout,
                    float4* __restrict__ kout,
                    int ngroups, int nwarps) {
    const int gw = (blockIdx.x * blockDim.x + threadIdx.x) >> 5;
    const int lane = threadIdx.x & 31;
    if (gw >= ngroups) return;

    const float s = 0.088388347648318447f;  // 1/sqrt(128)
    const unsigned long long s2 = pack2(s, s);

    // prime the pipeline
    long long base = (long long)gw * 64 + lane;
    float4 cq0 = __ldcs(qin + base);
    float4 cq1 = __ldcs(qin + base + 32);
    float4 ck0 = __ldcs(kin + base);
    float4 ck1 = __ldcs(kin + base + 32);

    for (int g = gw; g < ngroups; g += nwarps) {
        const long long cbase = (long long)g * 64 + lane;
        const int gn = g + nwarps;
        const long long nbase = (long long)gn * 64 + lane;

        // ---- prefetch next group BEFORE touching current data ----
        float4 nq0 = cq0, nq1 = cq1, nk0 = ck0, nk1 = ck1;
        if (gn < ngroups) {
            nq0 = __ldcs(qin + nbase);
            nq1 = __ldcs(qin + nbase + 32);
            nk0 = __ldcs(kin + nbase);
            nk1 = __ldcs(kin + nbase + 32);
        }

        // ---- rotate all 4 rows (interleaved chains) ----
        Row Q0 = stage12(cq0), Q1 = stage12(cq1);
        Row K0 = stage12(ck0), K1 = stage12(ck1);
#pragma unroll
        for (int i = 0; i < 5; i++) {
            const int m = 1 << i;
            const float sg = (lane & m) ? -1.0f : 1.0f;
            const unsigned long long sgn = pack2(sg, sg);
            xstage(Q0, sgn, m);
            xstage(Q1, sgn, m);
            xstage(K0, sgn, m);
            xstage(K1, sgn, m);
        }
        Q0.p0 = mul2(Q0.p0, s2); Q0.p1 = mul2(Q0.p1, s2);
        Q1.p0 = mul2(Q1.p0, s2); Q1.p1 = mul2(Q1.p1, s2);
        K0.p0 = mul2(K0.p0, s2); K0.p1 = mul2(K0.p1, s2);
        K1.p0 = mul2(K1.p0, s2); K1.p1 = mul2(K1.p1, s2);

        // ---- stores (streaming) ----
        __stcs(qout + cbase,      row_to_f4(Q0));
        __stcs(qout + cbase + 32, row_to_f4(Q1));
        quant_store(kout, cbase,      K0);
        quant_store(kout, cbase + 32, K1);

        // rotate pipeline registers
        cq0 = nq0; cq1 = nq1; ck0 = nk0; ck1 = nk1;
    }
}

extern "C" void kernel_launch(void* const* d_in, const int* in_sizes, int n_in,
                              void* d_out, int out_size) {
    const float4* qin = (const float4*)d_in[0];
    const float4* kin = (const float4*)d_in[1];

    const int n_elems = in_sizes[0];   // 33554432
    const int nrows = n_elems / 128;   // 262144
    const int ngroups = nrows / 2;     // 131072 (2 rows per group)

    float4* qout = (float4*)d_out;
    float4* kout = (float4*)d_out + (size_t)n_elems / 4;

    const int threads = 256;           // 8 warps/block
    const int blocks = 740;            // 148 SMs * 5 resident CTAs
    const int nwarps = blocks * (threads / 32);

    qk_rot_quant_kernel<<<blocks, threads>>>(qin, kin, qout, kout,
                                             ngroups, nwarps);
}

// round 8
// speedup vs baseline: 1.2671x; 1.2671x over previous
#include <cuda_runtime.h>

#define FULL_MASK 0xFFFFFFFFu

// ---- packed f32x2 helpers (sm_103a FFMA2/FMUL2 via PTX) ----
__device__ __forceinline__ unsigned long long pack2(float lo, float hi) {
    unsigned long long r;
    asm("mov.b64 %0, {%1, %2};" : "=l"(r) : "f"(lo), "f"(hi));
    return r;
}
__device__ __forceinline__ void unpack2(unsigned long long v, float& lo, float& hi) {
    asm("mov.b64 {%0, %1}, %2;" : "=f"(lo), "=f"(hi) : "l"(v));
}
__device__ __forceinline__ unsigned long long fma2(unsigned long long a,
                                                   unsigned long long b,
                                                   unsigned long long c) {
    unsigned long long r;
    asm("fma.rn.f32x2 %0, %1, %2, %3;" : "=l"(r) : "l"(a), "l"(b), "l"(c));
    return r;
}
__device__ __forceinline__ unsigned long long mul2(unsigned long long a,
                                                   unsigned long long b) {
    unsigned long long r;
    asm("mul.rn.f32x2 %0, %1, %2;" : "=l"(r) : "l"(a), "l"(b));
    return r;
}

// A 128-elem row's 4 per-lane floats, held as two packed f32x2.
struct Row { unsigned long long p0, p1; };  // (x,y), (z,w)

// In-register butterfly stages over index bits 0,1.
__device__ __forceinline__ Row stage12(float4 v) {
    float a = v.x + v.y, b = v.x - v.y;
    float c = v.z + v.w, d = v.z - v.w;
    Row r;
    r.p0 = pack2(a + c, b + d);
    r.p1 = pack2(a - c, b - d);
    return r;
}

// One cross-lane butterfly stage: v = fma(v, sgn, partner).
// sgn = -1 where (lane & mask), else +1. Bit-exact with (o-v)/(v+o).
__device__ __forceinline__ void xstage(Row& r, unsigned long long sgn, int mask) {
    float x, y, z, w;
    unpack2(r.p0, x, y);
    unpack2(r.p1, z, w);
    float ox = __shfl_xor_sync(FULL_MASK, x, mask);
    float oy = __shfl_xor_sync(FULL_MASK, y, mask);
    float oz = __shfl_xor_sync(FULL_MASK, z, mask);
    float ow = __shfl_xor_sync(FULL_MASK, w, mask);
    r.p0 = fma2(r.p0, sgn, pack2(ox, oy));
    r.p1 = fma2(r.p1, sgn, pack2(oz, ow));
}

__device__ __forceinline__ float4 row_to_f4(Row r) {
    float4 v;
    unpack2(r.p0, v.x, v.y);
    unpack2(r.p1, v.z, v.w);
    return v;
}

// Rotate 4 rows with interleaved shfl chains, then scale by 1/sqrt(128).
__device__ __forceinline__ void fwht4_scale(Row& R0, Row& R1, Row& R2, Row& R3,
                                            int lane) {
#pragma unroll
    for (int i = 0; i < 5; i++) {
        const int m = 1 << i;
        const float sg = (lane & m) ? -1.0f : 1.0f;
        const unsigned long long sgn = pack2(sg, sg);
        xstage(R0, sgn, m);
        xstage(R1, sgn, m);
        xstage(R2, sgn, m);
        xstage(R3, sgn, m);
    }
    const unsigned long long s2 =
        pack2(0.088388347648318447f, 0.088388347648318447f);
    R0.p0 = mul2(R0.p0, s2); R0.p1 = mul2(R0.p1, s2);
    R1.p0 = mul2(R1.p0, s2); R1.p1 = mul2(R1.p1, s2);
    R2.p0 = mul2(R2.p0, s2); R2.p1 = mul2(R2.p1, s2);
    R3.p0 = mul2(R3.p0, s2); R3.p1 = mul2(R3.p1, s2);
}

// 4-bit symmetric fake-quant of a rotated+scaled k row; streaming store.
__device__ __forceinline__ void quant_store(float4* __restrict__ p, long long idx, Row r) {
    float x, y, z, w;
    unpack2(r.p0, x, y);
    unpack2(r.p1, z, w);
    float amax = fmaxf(fmaxf(fabsf(x), fabsf(y)), fmaxf(fabsf(z), fabsf(w)));
#pragma unroll
    for (int m = 16; m >= 1; m >>= 1)
        amax = fmaxf(amax, __shfl_xor_sync(FULL_MASK, amax, m));
    if (amax == 0.0f) amax = 1.0f;
    const float qscale = amax / 7.0f;   // single rounding, matches reference
    const float qinv = 1.0f / qscale;
    float4 v;
    v.x = fminf(fmaxf(rintf(x * qinv), -8.0f), 7.0f) * qscale;
    v.y = fminf(fmaxf(rintf(y * qinv), -8.0f), 7.0f) * qscale;
    v.z = fminf(fmaxf(rintf(z * qinv), -8.0f), 7.0f) * qscale;
    v.w = fminf(fmaxf(rintf(w * qinv), -8.0f), 7.0f) * qscale;
    __stcs(p + idx, v);
}

// Heterogeneous grid: even blocks process Q (light), odd blocks process K
// (heavy). Modular bid->smid placement puts both kinds on every SM, so the
// memory system sees a steady interleave of loads/stores instead of the
// synchronized load-compute-store phases of a homogeneous kernel.
// Each warp: 4 contiguous rows of one tensor, 4x float4 loads up front.
__global__ void __launch_bounds__(256)
qk_rot_quant_kernel(const float4* __restrict__ qin,
                    const float4* __restrict__ kin,
                    float4* __restrict__ qout,
                    float4* __restrict__ kout,
                    int ngroups) {
    const int bid = blockIdx.x;
    const bool isK = bid & 1;
    // warp's group id within its tensor half
    const int gwarp = ((bid >> 1) * blockDim.x + threadIdx.x) >> 5;
    const int lane = threadIdx.x & 31;
    if (gwarp >= ngroups) return;

    const long long base = (long long)gwarp * 128 + lane;  // 4 rows * 32 f4

    if (!isK) {
        float4 a0 = __ldcs(qin + base);
        float4 a1 = __ldcs(qin + base + 32);
        float4 a2 = __ldcs(qin + base + 64);
        float4 a3 = __ldcs(qin + base + 96);
        Row R0 = stage12(a0), R1 = stage12(a1), R2 = stage12(a2), R3 = stage12(a3);
        fwht4_scale(R0, R1, R2, R3, lane);
        __stcs(qout + base,      row_to_f4(R0));
        __stcs(qout + base + 32, row_to_f4(R1));
        __stcs(qout + base + 64, row_to_f4(R2));
        __stcs(qout + base + 96, row_to_f4(R3));
    } else {
        float4 a0 = __ldcs(kin + base);
        float4 a1 = __ldcs(kin + base + 32);
        float4 a2 = __ldcs(kin + base + 64);
        float4 a3 = __ldcs(kin + base + 96);
        Row R0 = stage12(a0), R1 = stage12(a1), R2 = stage12(a2), R3 = stage12(a3);
        fwht4_scale(R0, R1, R2, R3, lane);
        quant_store(kout, base,      R0);
        quant_store(kout, base + 32, R1);
        quant_store(kout, base + 64, R2);
        quant_store(kout, base + 96, R3);
    }
}

extern "C" void kernel_launch(void* const* d_in, const int* in_sizes, int n_in,
                              void* d_out, int out_size) {
    const float4* qin = (const float4*)d_in[0];
    const float4* kin = (const float4*)d_in[1];

    const int n_elems = in_sizes[0];   // 33554432
    const int nrows = n_elems / 128;   // 262144
    const int ngroups = nrows / 4;     // 65536 groups of 4 rows (per tensor)

    float4* qout = (float4*)d_out;
    float4* kout = (float4*)d_out + (size_t)n_elems / 4;

    const int threads = 256;           // 8 warps = 32 rows per block
    const int groups_per_block = threads / 32;
    const int blocks_per_tensor = (ngroups + groups_per_block - 1) / groups_per_block;
    const int blocks = blocks_per_tensor * 2;  // even=Q, odd=K interleaved

    qk_rot_quant_kernel<<<blocks, threads>>>(qin, kin, qout, kout, ngroups);
}